// round 8
// baseline (speedup 1.0000x reference)
#include <cuda_runtime.h>
#include <cuda_bf16.h>
#include <cstdint>
#include <math.h>

#define BATCH 4
#define DIMC 128
#define HH 256
#define WW 256
#define WHF 129
#define HW 65536
#define NLAYERS 4
#define HID 512

typedef __nv_bfloat16 bf16;

// ================= device scratch (no allocation allowed) =====================
__device__ float  g_hf  [(size_t)BATCH * HW * DIMC];   // h, NHWC fp32 (residual/decoder)
__device__ bf16   g_ah  [(size_t)BATCH * HW * DIMC];   // h hi (GEMM1 / next-layer input)
__device__ bf16   g_al  [(size_t)BATCH * HW * DIMC];   // h lo
__device__ bf16   g_ch  [(size_t)BATCH * HW * HID];    // mlp hidden hi
__device__ bf16   g_cl  [(size_t)BATCH * HW * HID];    // mlp hidden lo
__device__ bf16   g_bh  [(size_t)BATCH * HW * DIMC];   // fft-output hi (oxo input)
__device__ bf16   g_bl  [(size_t)BATCH * HW * DIMC];   // fft-output lo
__device__ float  g_nchw[(size_t)BATCH * DIMC * HW];   // FFT real-space buffer, NCHW
__device__ float2 g_freq[(size_t)BATCH * DIMC * HH * WHF];
__device__ float2 g_filt[(size_t)NLAYERS * DIMC * HH * WHF];
__device__ float2 g_tw[128];
// bf16 weight splits [layer][O][K]
__device__ bf16 g_w1h[NLAYERS * HID * DIMC], g_w1l[NLAYERS * HID * DIMC];
__device__ bf16 g_w2h[NLAYERS * DIMC * HID], g_w2l[NLAYERS * DIMC * HID];
__device__ bf16 g_oxh[NLAYERS * DIMC * DIMC], g_oxl[NLAYERS * DIMC * DIMC];

// ================= helpers ====================================================
__device__ __forceinline__ uint32_t smem_u32(const void* p) {
    uint32_t a;
    asm("{ .reg .u64 t; cvta.to.shared.u64 t, %1; cvt.u32.u64 %0, t; }" : "=r"(a) : "l"(p));
    return a;
}
__device__ __forceinline__ void split2(float v, bf16& h, bf16& l) {
    h = __float2bfloat16(v);
    l = __float2bfloat16(v - __bfloat162float(h));
}
__device__ __forceinline__ float2 cmulf(float2 a, float2 b) {
    return make_float2(a.x * b.x - a.y * b.y, a.x * b.y + a.y * b.x);
}
__device__ __forceinline__ int brev8(int i) { return __brev(i) >> 24; }

__device__ __forceinline__ void ldsm_x4(uint32_t& r0, uint32_t& r1, uint32_t& r2,
                                        uint32_t& r3, uint32_t addr) {
    asm volatile("ldmatrix.sync.aligned.m8n8.x4.shared.b16 {%0,%1,%2,%3}, [%4];"
                 : "=r"(r0), "=r"(r1), "=r"(r2), "=r"(r3) : "r"(addr));
}
__device__ __forceinline__ void ldsm_x2(uint32_t& r0, uint32_t& r1, uint32_t addr) {
    asm volatile("ldmatrix.sync.aligned.m8n8.x2.shared.b16 {%0,%1}, [%2];"
                 : "=r"(r0), "=r"(r1) : "r"(addr));
}
__device__ __forceinline__ void mma16816(float* c, const uint32_t* a, const uint32_t* b) {
    asm volatile(
        "mma.sync.aligned.m16n8k16.row.col.f32.bf16.bf16.f32 "
        "{%0,%1,%2,%3}, {%4,%5,%6,%7}, {%8,%9}, {%0,%1,%2,%3};"
        : "+f"(c[0]), "+f"(c[1]), "+f"(c[2]), "+f"(c[3])
        : "r"(a[0]), "r"(a[1]), "r"(a[2]), "r"(a[3]), "r"(b[0]), "r"(b[1]));
}
__device__ __forceinline__ void cp_async16(uint32_t s_dst, const void* g_src) {
    asm volatile("cp.async.cg.shared.global [%0], [%1], 16;" :: "r"(s_dst), "l"(g_src));
}
__device__ __forceinline__ void cp_async_commit_wait0() {
    asm volatile("cp.async.commit_group;" ::: "memory");
    asm volatile("cp.async.wait_group 0;" ::: "memory");
}

// ================= misc prep kernels =========================================
__global__ void init_tw_k() {
    int t = threadIdx.x;
    double ang = -2.0 * 3.14159265358979323846 * (double)t / 256.0;
    g_tw[t] = make_float2((float)cos(ang), (float)sin(ang));
}

__global__ void fill_filt_k(const float* __restrict__ mags, const float* __restrict__ phases) {
    size_t idx = (size_t)blockIdx.x * blockDim.x + threadIdx.x;
    const size_t total = (size_t)NLAYERS * DIMC * HH * WHF;
    if (idx >= total) return;
    int wh = (int)(idx % WHF);
    size_t r = idx / WHF;
    int hh = (int)(r % HH);
    int ry = (hh < 128) ? hh : hh - 256;
    bool mask = (wh * wh + ry * ry) <= 16384;
    float m = mags[idx], p = phases[idx];
    float sg = 1.0f / (1.0f + __expf(-m));
    float sp, cp;
    sincosf(p, &sp, &cp);
    float sc = mask ? (sg * (1.0f / 65536.0f)) : 0.0f;
    g_filt[idx] = make_float2(sc * cp, sc * sp);
}

__global__ void split_w_k(const float* __restrict__ s, bf16* __restrict__ h,
                          bf16* __restrict__ l, int n) {
    int i = blockIdx.x * blockDim.x + threadIdx.x;
    if (i >= n) return;
    bf16 hh, ll;
    split2(s[i], hh, ll);
    h[i] = hh; l[i] = ll;
}

// encoder: NHWC h + bf16 split pairs
__global__ void __launch_bounds__(256) encoder_k(const float* __restrict__ x,
                                                 const float* __restrict__ ew,
                                                 const float* __restrict__ eb,
                                                 const float* __restrict__ pos) {
    __shared__ float ts[128][33];
    __shared__ float xs0[32], xs1[32];
    int b = blockIdx.y;
    int p0 = blockIdx.x * 32;
    for (int i = threadIdx.x; i < 128 * 32; i += 256) {
        int c = i >> 5, p = i & 31;
        ts[c][p] = pos[(((size_t)c) << 16) + p0 + p];
    }
    if (threadIdx.x < 32) {
        xs0[threadIdx.x] = x[(((size_t)(b * 2 + 0)) << 16) + p0 + threadIdx.x];
        xs1[threadIdx.x] = x[(((size_t)(b * 2 + 1)) << 16) + p0 + threadIdx.x];
    }
    __syncthreads();
    for (int i = threadIdx.x; i < 32 * 128; i += 256) {
        int p = i >> 7, c = i & 127;
        float v = (__ldg(&ew[c * 2]) * xs0[p] + __ldg(&ew[c * 2 + 1]) * xs1[p] + __ldg(&eb[c])) * 8.0f
                  + ts[c][p];
        size_t o = ((size_t)b * HW + p0 + p) * DIMC + c;
        g_hf[o] = v;
        bf16 hh, ll; split2(v, hh, ll);
        g_ah[o] = hh; g_al[o] = ll;
    }
}

__global__ void __launch_bounds__(256) decoder_k(const float* __restrict__ dw,
                                                 const float* __restrict__ db,
                                                 float* __restrict__ out) {
    __shared__ float ts[32][132];
    int b = blockIdx.y;
    int p0 = blockIdx.x * 32;
    const float* src = g_hf + ((size_t)b * HW + p0) * DIMC;
    for (int i = threadIdx.x; i < 32 * 128; i += 256) {
        int p = i >> 7, c = i & 127;
        ts[p][c] = src[i];
    }
    __syncthreads();
    if (threadIdx.x < 64) {
        int p = threadIdx.x >> 1, o = threadIdx.x & 1;
        const float* w = dw + o * DIMC;
        float a = 0.f;
#pragma unroll 8
        for (int c = 0; c < 128; ++c) a += __ldg(&w[c]) * ts[p][c];
        out[(((size_t)(b * 2 + o)) << 16) + p0 + p] = (a + __ldg(&db[o])) * 0.125f;
    }
}

// NCHW fp32 -> NHWC bf16 hi/lo (after FFT, feeding oxo GEMM)
__global__ void __launch_bounds__(256) nchw_to_pair_k(const float* __restrict__ src,
                                                      bf16* __restrict__ dh,
                                                      bf16* __restrict__ dl) {
    __shared__ float ts[128][33];
    int b = blockIdx.y;
    int p0 = blockIdx.x * 32;
    const float* s = src + (((size_t)b * DIMC) << 16) + p0;
    for (int i = threadIdx.x; i < 128 * 32; i += 256) {
        int c = i >> 5, p = i & 31;
        ts[c][p] = s[(((size_t)c) << 16) + p];
    }
    __syncthreads();
    for (int i = threadIdx.x; i < 32 * 128; i += 256) {
        int p = i >> 7, c = i & 127;
        float v = ts[c][p];
        bf16 hh, ll; split2(v, hh, ll);
        size_t o = ((size_t)b * HW + p0 + p) * DIMC + c;
        dh[o] = hh; dl[o] = ll;
    }
}

// ================= FFT kernels ================================================
__device__ __forceinline__ void fft256(float2* s, const float2* tw, int t) {
#pragma unroll
    for (int len = 2; len <= 256; len <<= 1) {
        __syncthreads();
        int half = len >> 1;
        int j = t & (half - 1);
        int i = ((t & ~(half - 1)) << 1) | j;
        float2 w = tw[j * (256 / len)];
        float2 u = s[i];
        float2 v = cmulf(s[i + half], w);
        s[i]        = make_float2(u.x + v.x, u.y + v.y);
        s[i + half] = make_float2(u.x - v.x, u.y - v.y);
    }
    __syncthreads();
}

__global__ void __launch_bounds__(128) fft_rows_fwd_k(const float* __restrict__ in) {
    __shared__ float2 s[256];
    __shared__ float2 tw[128];
    int t = threadIdx.x;
    tw[t] = g_tw[t];
    const float* row = in + (size_t)blockIdx.x * WW;
    s[brev8(t)]       = make_float2(row[t], 0.f);
    s[brev8(t + 128)] = make_float2(row[t + 128], 0.f);
    fft256(s, tw, t);
    float2* outp = g_freq + (size_t)blockIdx.x * WHF;
    outp[t] = s[t];
    if (t == 0) outp[128] = s[128];
}

// Column FFT + filter + inverse column FFT, 8 adjacent columns per block
#define CB 8
__global__ void __launch_bounds__(256) fft_cols_filter_k(int layer) {
    __shared__ float2 s [256][CB + 1];
    __shared__ float2 s2[256][CB + 1];
    __shared__ float2 tw[128];
    const int t = threadIdx.x;
    if (t < 128) tw[t] = g_tw[t];
    const int col0 = blockIdx.x * CB;
    const int c = blockIdx.y, b = blockIdx.z;
    float2* base = g_freq + ((size_t)(b * DIMC + c) * HH) * WHF;

#pragma unroll
    for (int k = 0; k < 8; ++k) {
        int idx = t + k * 256;
        int h = idx >> 3, cl = idx & 7;
        float2 v = (col0 + cl < WHF) ? base[(size_t)h * WHF + col0 + cl]
                                     : make_float2(0.f, 0.f);
        s[brev8(h)][cl] = v;
    }
#pragma unroll
    for (int len = 2; len <= 256; len <<= 1) {
        __syncthreads();
        int half = len >> 1;
#pragma unroll
        for (int k = 0; k < 4; ++k) {
            int q = t + k * 256;
            int cl = q & 7, bfy = q >> 3;
            int j = bfy & (half - 1);
            int i = ((bfy & ~(half - 1)) << 1) | j;
            float2 w = tw[j * (256 / len)];
            float2 u = s[i][cl];
            float2 v = cmulf(s[i + half][cl], w);
            s[i][cl]        = make_float2(u.x + v.x, u.y + v.y);
            s[i + half][cl] = make_float2(u.x - v.x, u.y - v.y);
        }
    }
    __syncthreads();
    const float2* f = g_filt + ((size_t)layer * DIMC + c) * HH * WHF;
#pragma unroll
    for (int k = 0; k < 8; ++k) {
        int idx = t + k * 256;
        int h = idx >> 3, cl = idx & 7;
        float2 fv = (col0 + cl < WHF) ? f[(size_t)h * WHF + col0 + cl]
                                      : make_float2(0.f, 0.f);
        float2 v = cmulf(s[h][cl], fv);
        s2[brev8(h)][cl] = make_float2(v.x, -v.y);
    }
#pragma unroll
    for (int len = 2; len <= 256; len <<= 1) {
        __syncthreads();
        int half = len >> 1;
#pragma unroll
        for (int k = 0; k < 4; ++k) {
            int q = t + k * 256;
            int cl = q & 7, bfy = q >> 3;
            int j = bfy & (half - 1);
            int i = ((bfy & ~(half - 1)) << 1) | j;
            float2 w = tw[j * (256 / len)];
            float2 u = s2[i][cl];
            float2 v = cmulf(s2[i + half][cl], w);
            s2[i][cl]        = make_float2(u.x + v.x, u.y + v.y);
            s2[i + half][cl] = make_float2(u.x - v.x, u.y - v.y);
        }
    }
    __syncthreads();
#pragma unroll
    for (int k = 0; k < 8; ++k) {
        int idx = t + k * 256;
        int h = idx >> 3, cl = idx & 7;
        if (col0 + cl < WHF) {
            float2 r = s2[h][cl];
            base[(size_t)h * WHF + col0 + cl] = make_float2(r.x, -r.y);
        }
    }
}

__global__ void __launch_bounds__(128) fft_rows_inv_k(float* __restrict__ out) {
    __shared__ float2 s[256];
    __shared__ float2 tw[128];
    int t = threadIdx.x;
    tw[t] = g_tw[t];
    const float2* in = g_freq + (size_t)blockIdx.x * WHF;
    float2 a = in[t];
    float2 bb;
    if (t == 0) bb = in[128];
    else {
        float2 m = in[128 - t];
        bb = make_float2(m.x, -m.y);
    }
    s[brev8(t)]       = make_float2(a.x, -a.y);
    s[brev8(t + 128)] = make_float2(bb.x, -bb.y);
    fft256(s, tw, t);
    float* o = out + (size_t)blockIdx.x * WW;
    o[t]       = s[t].x;
    o[t + 128] = s[t + 128].x;
}

// ================= HMMA (mma.sync bf16) GEMM =================================
// Out(pixels, O) = X(pixels, K) @ W(O, K)^T, per batch, NHWC.  3 passes of
// mma.sync.m16n8k16 (hi*hi + hi*lo + lo*hi) with fp32 register accumulators.
// CTA tile 128x128, 8 warps (2m x 4n), warp tile 64x32, BK = 64.
// smem: 4 tiles of 128 rows x 128B (SW128 swizzle): Ah, Al, Bh, Bl = 64 KB.
// Tiles staged via cp.async; 2 CTAs/SM give cross-CTA load/compute overlap.
#define GEMM_SMEM 65536

__device__ __forceinline__ void load_tile_async(const bf16* __restrict__ g, int pitch,
                                                uint32_t s_dst, int t /*0..255*/) {
#pragma unroll
    for (int i = 0; i < 4; ++i) {
        int u = t + i * 256;                // 16B-chunk id, 0..1023
        int r = u >> 3, c = u & 7;
        cp_async16(s_dst + r * 128 + ((c ^ (r & 7)) << 4),
                   g + (size_t)r * pitch + c * 8);
    }
}

// EPI: 0 = +bias -> NCHW fp32 ; 1 = silu(+bias) -> NHWC bf16 pair (width HID)
//      2 = +bias + residual -> NHWC fp32 + bf16 pair (width DIMC)
template <int KTOT, int EPI>
__global__ void __launch_bounds__(256, 2) hmma_gemm_k(
    const bf16* __restrict__ Ah, const bf16* __restrict__ Al,
    const bf16* __restrict__ Bh, const bf16* __restrict__ Bl,
    const float* __restrict__ bias,
    const float* __restrict__ resid,
    float* __restrict__ outF,
    bf16* __restrict__ outH, bf16* __restrict__ outL) {
    extern __shared__ char smem[];
    const int t = threadIdx.x;
    const int w = t >> 5, l = t & 31;
    const int wm = w >> 2, wn = w & 3;
    const int gid = l >> 2, tig = l & 3;
    const int bz = blockIdx.z;
    const int px0 = blockIdx.y * 128;
    const int n0 = (EPI == 1) ? blockIdx.x * 128 : 0;
    const size_t pixbase = (size_t)bz * HW + px0;

    const bf16* gAh = Ah + pixbase * KTOT;
    const bf16* gAl = Al + pixbase * KTOT;
    const bf16* gBh = Bh + (size_t)n0 * KTOT;
    const bf16* gBl = Bl + (size_t)n0 * KTOT;

    const uint32_t sb = smem_u32(smem);
    const uint32_t sAh = sb, sAl = sb + 16384, sBh = sb + 32768, sBl = sb + 49152;

    float acc[4][4][4];
#pragma unroll
    for (int mf = 0; mf < 4; ++mf)
#pragma unroll
        for (int nf = 0; nf < 4; ++nf)
#pragma unroll
            for (int r = 0; r < 4; ++r) acc[mf][nf][r] = 0.f;

    // ldmatrix per-lane address components (row within tile, 16B chunk within row)
    const uint32_t a_row = wm * 64 + (l & 15);       // + mf*16
    const uint32_t a_ch  = (uint32_t)(l >> 4);       // + ks*2
    const uint32_t b_row = wn * 32 + (l & 7);        // + nf*8
    const uint32_t b_ch  = (uint32_t)((l >> 3) & 1); // + ks*2

    for (int k0 = 0; k0 < KTOT; k0 += 64) {
        __syncthreads();
        load_tile_async(gAh + k0, KTOT, sAh, t);
        load_tile_async(gAl + k0, KTOT, sAl, t);
        load_tile_async(gBh + k0, KTOT, sBh, t);
        load_tile_async(gBl + k0, KTOT, sBl, t);
        cp_async_commit_wait0();
        __syncthreads();
#pragma unroll
        for (int ks = 0; ks < 4; ++ks) {
            uint32_t bh[4][2], bl[4][2];
#pragma unroll
            for (int nf = 0; nf < 4; ++nf) {
                uint32_t row = b_row + nf * 8;
                uint32_t off = row * 128 + (((b_ch + ks * 2) ^ (row & 7)) << 4);
                ldsm_x2(bh[nf][0], bh[nf][1], sBh + off);
                ldsm_x2(bl[nf][0], bl[nf][1], sBl + off);
            }
#pragma unroll
            for (int mf = 0; mf < 4; ++mf) {
                uint32_t ah[4], al[4];
                uint32_t row = a_row + mf * 16;
                uint32_t off = row * 128 + (((a_ch + ks * 2) ^ (row & 7)) << 4);
                ldsm_x4(ah[0], ah[1], ah[2], ah[3], sAh + off);
                ldsm_x4(al[0], al[1], al[2], al[3], sAl + off);
#pragma unroll
                for (int nf = 0; nf < 4; ++nf) {
                    mma16816(acc[mf][nf], ah, bh[nf]);
                    mma16816(acc[mf][nf], ah, bl[nf]);
                    mma16816(acc[mf][nf], al, bh[nf]);
                }
            }
        }
    }

    // ---- epilogue ----
#pragma unroll
    for (int mf = 0; mf < 4; ++mf) {
#pragma unroll
        for (int r = 0; r < 2; ++r) {             // c{0,1} then c{2,3} (row +8)
            int pix = px0 + wm * 64 + mf * 16 + gid + r * 8;
            size_t pixg = (size_t)bz * HW + pix;
#pragma unroll
            for (int nf = 0; nf < 4; ++nf) {
                int ch = wn * 32 + nf * 8 + 2 * tig;
                float c0 = acc[mf][nf][2 * r], c1 = acc[mf][nf][2 * r + 1];
                if (EPI == 0) {
                    float s0 = c0 + __ldg(&bias[ch]);
                    float s1 = c1 + __ldg(&bias[ch + 1]);
                    outF[(((size_t)(bz * DIMC + ch))     << 16) + pix] = s0;
                    outF[(((size_t)(bz * DIMC + ch + 1)) << 16) + pix] = s1;
                } else if (EPI == 1) {
                    float s0 = c0 + __ldg(&bias[n0 + ch]);
                    float s1 = c1 + __ldg(&bias[n0 + ch + 1]);
                    s0 = s0 / (1.0f + __expf(-s0));
                    s1 = s1 / (1.0f + __expf(-s1));
                    bf16 h0, l0, h1, l1;
                    split2(s0, h0, l0); split2(s1, h1, l1);
                    size_t o = pixg * HID + n0 + ch;
                    *reinterpret_cast<__nv_bfloat162*>(outH + o) = __nv_bfloat162(h0, h1);
                    *reinterpret_cast<__nv_bfloat162*>(outL + o) = __nv_bfloat162(l0, l1);
                } else {
                    size_t o = pixg * DIMC + ch;
                    float2 rv = *reinterpret_cast<const float2*>(resid + o);
                    float s0 = c0 + __ldg(&bias[ch])     + rv.x;
                    float s1 = c1 + __ldg(&bias[ch + 1]) + rv.y;
                    *reinterpret_cast<float2*>(outF + o) = make_float2(s0, s1);
                    bf16 h0, l0, h1, l1;
                    split2(s0, h0, l0); split2(s1, h1, l1);
                    *reinterpret_cast<__nv_bfloat162*>(outH + o) = __nv_bfloat162(h0, h1);
                    *reinterpret_cast<__nv_bfloat162*>(outL + o) = __nv_bfloat162(l0, l1);
                }
            }
        }
    }
}

// ================= launch =====================================================
extern "C" void kernel_launch(void* const* d_in, const int* in_sizes, int n_in,
                              void* d_out, int out_size) {
    const float* x      = (const float*)d_in[0];
    const float* enc_w  = (const float*)d_in[1];
    const float* enc_b  = (const float*)d_in[2];
    const float* pos    = (const float*)d_in[3];
    const float* mlp_w1 = (const float*)d_in[4];
    const float* mlp_b1 = (const float*)d_in[5];
    const float* mlp_w2 = (const float*)d_in[6];
    const float* mlp_b2 = (const float*)d_in[7];
    const float* mags   = (const float*)d_in[8];
    const float* phases = (const float*)d_in[9];
    const float* oxo_w  = (const float*)d_in[10];
    const float* oxo_b  = (const float*)d_in[11];
    const float* dec_w  = (const float*)d_in[12];
    const float* dec_b  = (const float*)d_in[13];
    float* out = (float*)d_out;

    float *p_hf, *p_nchw;
    bf16 *p_ah, *p_al, *p_ch, *p_cl, *p_bh, *p_bl;
    bf16 *p_w1h, *p_w1l, *p_w2h, *p_w2l, *p_oxh, *p_oxl;
    cudaGetSymbolAddress((void**)&p_hf, g_hf);
    cudaGetSymbolAddress((void**)&p_nchw, g_nchw);
    cudaGetSymbolAddress((void**)&p_ah, g_ah);
    cudaGetSymbolAddress((void**)&p_al, g_al);
    cudaGetSymbolAddress((void**)&p_ch, g_ch);
    cudaGetSymbolAddress((void**)&p_cl, g_cl);
    cudaGetSymbolAddress((void**)&p_bh, g_bh);
    cudaGetSymbolAddress((void**)&p_bl, g_bl);
    cudaGetSymbolAddress((void**)&p_w1h, g_w1h);
    cudaGetSymbolAddress((void**)&p_w1l, g_w1l);
    cudaGetSymbolAddress((void**)&p_w2h, g_w2h);
    cudaGetSymbolAddress((void**)&p_w2l, g_w2l);
    cudaGetSymbolAddress((void**)&p_oxh, g_oxh);
    cudaGetSymbolAddress((void**)&p_oxl, g_oxl);

    cudaFuncSetAttribute((const void*)hmma_gemm_k<128, 1>,
                         cudaFuncAttributeMaxDynamicSharedMemorySize, GEMM_SMEM);
    cudaFuncSetAttribute((const void*)hmma_gemm_k<512, 0>,
                         cudaFuncAttributeMaxDynamicSharedMemorySize, GEMM_SMEM);
    cudaFuncSetAttribute((const void*)hmma_gemm_k<128, 2>,
                         cudaFuncAttributeMaxDynamicSharedMemorySize, GEMM_SMEM);

    init_tw_k<<<1, 128>>>();
    {
        const size_t total = (size_t)NLAYERS * DIMC * HH * WHF;
        fill_filt_k<<<(int)((total + 255) / 256), 256>>>(mags, phases);
    }
    split_w_k<<<(NLAYERS * HID * DIMC + 255) / 256, 256>>>(mlp_w1, p_w1h, p_w1l, NLAYERS * HID * DIMC);
    split_w_k<<<(NLAYERS * DIMC * HID + 255) / 256, 256>>>(mlp_w2, p_w2h, p_w2l, NLAYERS * DIMC * HID);
    split_w_k<<<(NLAYERS * DIMC * DIMC + 255) / 256, 256>>>(oxo_w, p_oxh, p_oxl, NLAYERS * DIMC * DIMC);

    encoder_k<<<dim3(HW / 32, BATCH), 256>>>(x, enc_w, enc_b, pos);

    const int ROWS = BATCH * DIMC * HH;
    for (int i = 0; i < NLAYERS; ++i) {
        // x1 = silu(W1 @ h + b1) -> bf16 pair (NHWC, HID). x = n-block (fast) for L2 A-reuse.
        hmma_gemm_k<128, 1><<<dim3(HID / 128, HW / 128, BATCH), 256, GEMM_SMEM>>>(
            p_ah, p_al, p_w1h + (size_t)i * HID * DIMC, p_w1l + (size_t)i * HID * DIMC,
            mlp_b1 + (size_t)i * HID, nullptr, nullptr, p_ch, p_cl);
        // x1 = W2 @ x1 + b2 -> NCHW fp32 (FFT input)
        hmma_gemm_k<512, 0><<<dim3(1, HW / 128, BATCH), 256, GEMM_SMEM>>>(
            p_ch, p_cl, p_w2h + (size_t)i * DIMC * HID, p_w2l + (size_t)i * DIMC * HID,
            mlp_b2 + (size_t)i * DIMC, nullptr, p_nchw, nullptr, nullptr);
        // spectral conv
        fft_rows_fwd_k<<<ROWS, 128>>>(p_nchw);
        fft_cols_filter_k<<<dim3((WHF + CB - 1) / CB, DIMC, BATCH), 256>>>(i);
        fft_rows_inv_k<<<ROWS, 128>>>(p_nchw);
        // NCHW -> NHWC bf16 pair
        nchw_to_pair_k<<<dim3(HW / 32, BATCH), 256>>>(p_nchw, p_bh, p_bl);
        // h = oxo @ x1 + b + h  (writes h fp32 + next-layer bf16 pair)
        hmma_gemm_k<128, 2><<<dim3(1, HW / 128, BATCH), 256, GEMM_SMEM>>>(
            p_bh, p_bl, p_oxh + (size_t)i * DIMC * DIMC, p_oxl + (size_t)i * DIMC * DIMC,
            oxo_b + (size_t)i * DIMC, p_hf, p_hf, p_ah, p_al);
    }
    decoder_k<<<dim3(HW / 32, BATCH), 256>>>(dec_w, dec_b, out);
}